// round 10
// baseline (speedup 1.0000x reference)
#include <cuda_runtime.h>
#include <cuda_fp16.h>
#include <math.h>
#include <stdint.h>

#define NMAX 100000
#define EMAX 1600000
#define DD 64
#define SCB 200          // scan blocks; 200*512 = 102400 >= NMAX; co-resident

typedef unsigned long long u64;

// ---------------- device scratch (no allocations allowed) ----------------
__device__ int    g_counts[NMAX];        // zeroed by scan_fused after use
__device__ int    g_fill[NMAX];
__device__ int    g_rowptr[NMAX + 1];
__device__ int    g_esrc[EMAX];          // BYTE offsets: src * 128
__device__ int    g_bsum[SCB];
__device__ unsigned long long g_barctr;  // monotonic, never reset (replay-safe)
__device__ __half g_yh[(size_t)NMAX * DD];
__device__ float  g_agg[(size_t)NMAX * DD];
__device__ float  g_M1[DD * DD];
__device__ float  g_M2[DD * DD];
__device__ float  g_v[DD];
__device__ float  g_bias;

// inline edge-dtype detect: warp 0 ballots 32 odd words (int64 => all zero)
__device__ __forceinline__ int detect_is64_block(const void* edges, int* s64) {
    if (threadIdx.x < 32) {
        const int* w = (const int*)edges;
        int v = w[2 * threadIdx.x + 1];
        unsigned nz = __ballot_sync(0xffffffffu, v != 0);
        if (threadIdx.x == 0) *s64 = (nz == 0u) ? 1 : 0;
    }
    __syncthreads();
    return *s64;
}

__global__ void hist_kernel(const void* __restrict__ edges, int E) {
    __shared__ int s64;
    int is64 = detect_is64_block(edges, &s64);
    int e = blockIdx.x * blockDim.x + threadIdx.x;
    if (e >= E) return;
    int dst;
    if (is64) dst = (int)((const long long*)edges)[E + e];
    else      dst = ((const int*)edges)[E + e];
    atomicAdd(&g_counts[dst], 1);
}

// ---------------- fused: matprep + single-kernel scan ---------------------
__device__ __forceinline__ void grid_barrier_200() {
    __syncthreads();
    if (threadIdx.x == 0) {
        __threadfence();
        unsigned long long my = atomicAdd(&g_barctr, 1ULL) + 1ULL;
        unsigned long long target = ((my + SCB - 1) / SCB) * (unsigned long long)SCB;
        while (atomicAdd(&g_barctr, 0ULL) < target) { }
        __threadfence();
    }
    __syncthreads();
}

__global__ void scan_fused(const float* __restrict__ Wp,
                           const float* __restrict__ Wt,
                           const float* __restrict__ Wout,
                           const float* __restrict__ bout, int N) {
    int b = blockIdx.x, t = threadIdx.x;

    // ---- matprep on blocks 0..15 (4096 lanes) ----
    if (b < 16) {
        int id = b * 256 + t;
        int i = id >> 6, k = id & 63;
        float s1 = 0.f, s2 = 0.f;
#pragma unroll
        for (int m = 0; m < DD; m++) {
            s1 += Wp[1 * DD * DD + i * DD + m] * Wt[0 * DD * DD + m * DD + k];
            s2 += Wp[2 * DD * DD + i * DD + m] * Wt[1 * DD * DD + m * DD + k];
        }
        g_M1[id] = s1;
        g_M2[id] = s2;
        if (i == 0) {
            float sv = 0.f;
#pragma unroll
            for (int m = 0; m < DD; m++)
                sv += Wout[m] * Wt[2 * DD * DD + m * DD + k];
            g_v[k] = sv;
        }
        if (id == 0) g_bias = bout[0];
    }

    // ---- phase 1: block sum over its 512-element chunk ----
    __shared__ int sm[256];
    int base = b * 512 + t * 2;
    int c0 = (base < N) ? g_counts[base] : 0;
    int c1 = (base + 1 < N) ? g_counts[base + 1] : 0;
    int s = c0 + c1;
    sm[t] = s;
    __syncthreads();
    for (int off = 128; off; off >>= 1) {
        if (t < off) sm[t] += sm[t + off];
        __syncthreads();
    }
    if (t == 0) g_bsum[b] = sm[0];

    grid_barrier_200();

    // ---- phase 2a: block offset = exclusive prefix of g_bsum ----
    __shared__ int sb[256];
    sb[t] = (t < SCB) ? g_bsum[t] : 0;
    __syncthreads();
    for (int off = 1; off < 256; off <<= 1) {
        int v = (t >= off) ? sb[t - off] : 0;
        __syncthreads();
        sb[t] += v;
        __syncthreads();
    }
    int blockoff = (b == 0) ? 0 : sb[b - 1];
    if (b == SCB - 1 && t == 0) g_rowptr[N] = sb[SCB - 1];

    // ---- phase 2b: local exclusive scan + write + zero counts ----
    sm[t] = s;
    __syncthreads();
    for (int off = 1; off < 256; off <<= 1) {
        int v = (t >= off) ? sm[t - off] : 0;
        __syncthreads();
        sm[t] += v;
        __syncthreads();
    }
    int pre = sm[t] - s + blockoff;
    if (base < N)     { g_rowptr[base] = pre;          g_fill[base] = pre;          g_counts[base] = 0; }
    if (base + 1 < N) { g_rowptr[base + 1] = pre + c0; g_fill[base + 1] = pre + c0; g_counts[base + 1] = 0; }
}

__global__ void scatter_kernel(const void* __restrict__ edges, int E) {
    __shared__ int s64;
    int is64 = detect_is64_block(edges, &s64);
    int e = blockIdx.x * blockDim.x + threadIdx.x;
    if (e >= E) return;
    int src, dst;
    if (is64) {
        const long long* p = (const long long*)edges;
        src = (int)p[e]; dst = (int)p[E + e];
    } else {
        const int* p = (const int*)edges;
        src = p[e]; dst = p[E + e];
    }
    int pos = atomicAdd(&g_fill[dst], 1);
    g_esrc[pos] = src << 7;              // byte offset into fp16 rows (64*2B)
}

// ---------------- GEMM: broadcast-B FFMA2 -------------------------------
// 256 threads = 8 warps. Tile: 32 rows x 64 cols. Warp w owns cols 8w..8w+7
// across all 32 rows; thread = 1 row x 8 cols. A: per-lane LDS.128 (conflict-
// free). B: warp-uniform LDS.128 (broadcast = 1 crossbar access). 16 FFMA2
// per chunk; B float4 reinterpreted as two reg-pairs (free).
#define SXS 68
__global__ void gemm_kernel(const float* __restrict__ x,
                            const float* __restrict__ M,
                            __half* __restrict__ out, int N) {
    __shared__ float sx[32][SXS];
    __shared__ float sMt[DD][SXS];   // sMt[k][col] = M[col][k]
    int t = threadIdx.x;
    int w = t >> 5, lane = t & 31;
    int base = blockIdx.x * 32;

    // stage M transposed: 1024 float4, 4 per thread
#pragma unroll
    for (int i = 0; i < 4; i++) {
        int v = t + 256 * i;
        int r = v >> 4;              // M row (= output col)
        int c4 = (v & 15) * 4;       // k base
        float4 mv = *(const float4*)&M[r * DD + c4];
        sMt[c4][r] = mv.x; sMt[c4 + 1][r] = mv.y;
        sMt[c4 + 2][r] = mv.z; sMt[c4 + 3][r] = mv.w;
    }
    // stage x tile: 512 float4, 2 per thread
#pragma unroll
    for (int i = 0; i < 2; i++) {
        int v = t + 256 * i;
        int r = v >> 4;
        int c4 = (v & 15) * 4;
        float4 xv = make_float4(0.f, 0.f, 0.f, 0.f);
        if (base + r < N)
            xv = *(const float4*)&x[(size_t)(base + r) * DD + c4];
        *(float4*)&sx[r][c4] = xv;
    }
    __syncthreads();

    int tc = w * 8;
    u64 acc2[4] = {0ULL, 0ULL, 0ULL, 0ULL};   // col pairs (0,1)(2,3)(4,5)(6,7)

#pragma unroll
    for (int k = 0; k < DD; k += 4) {
        float4 a = *(const float4*)&sx[lane][k];
#pragma unroll
        for (int kk = 0; kk < 4; kk++) {
            float av = (kk == 0) ? a.x : (kk == 1) ? a.y : (kk == 2) ? a.z : a.w;
            u64 aa;
            asm("mov.b64 %0, {%1, %1};" : "=l"(aa) : "f"(av));
            float4 blo = *(const float4*)&sMt[k + kk][tc];       // cols tc..tc+3
            float4 bhi = *(const float4*)&sMt[k + kk][tc + 4];   // cols tc+4..tc+7
            u64 b0 = *(const u64*)&blo.x;
            u64 b1 = *(const u64*)&blo.z;
            u64 b2 = *(const u64*)&bhi.x;
            u64 b3 = *(const u64*)&bhi.z;
            asm("fma.rn.f32x2 %0, %1, %2, %0;" : "+l"(acc2[0]) : "l"(aa), "l"(b0));
            asm("fma.rn.f32x2 %0, %1, %2, %0;" : "+l"(acc2[1]) : "l"(aa), "l"(b1));
            asm("fma.rn.f32x2 %0, %1, %2, %0;" : "+l"(acc2[2]) : "l"(aa), "l"(b2));
            asm("fma.rn.f32x2 %0, %1, %2, %0;" : "+l"(acc2[3]) : "l"(aa), "l"(b3));
        }
    }

    int row = base + lane;
    if (row < N) {
        float c0, c1, c2, c3, c4, c5, c6, c7;
        asm("mov.b64 {%0, %1}, %2;" : "=f"(c0), "=f"(c1) : "l"(acc2[0]));
        asm("mov.b64 {%0, %1}, %2;" : "=f"(c2), "=f"(c3) : "l"(acc2[1]));
        asm("mov.b64 {%0, %1}, %2;" : "=f"(c4), "=f"(c5) : "l"(acc2[2]));
        asm("mov.b64 {%0, %1}, %2;" : "=f"(c6), "=f"(c7) : "l"(acc2[3]));
        __half2 h0 = __floats2half2_rn(c0, c1);
        __half2 h1 = __floats2half2_rn(c2, c3);
        __half2 h2 = __floats2half2_rn(c4, c5);
        __half2 h3 = __floats2half2_rn(c6, c7);
        uint4 pack;
        pack.x = *(const unsigned*)&h0;
        pack.y = *(const unsigned*)&h1;
        pack.z = *(const unsigned*)&h2;
        pack.w = *(const unsigned*)&h3;
        *(uint4*)&out[(size_t)row * DD + tc] = pack;
    }
}

// ---------------- aggregation core (fp16 gather, uniform-ldg indices) -----
__device__ __forceinline__ void agg_core_h(const __half* __restrict__ yh,
                                           int beg, int end, int lane,
                                           __half2& m01, __half2& m23) {
    const __half2 ninf = __float2half2_rn(-INFINITY);
    m01 = ninf; m23 = ninf;
    const char* Y = (const char*)yh;
    int half_id = lane >> 4;
    int qb = (lane & 15) * 8;
    int p = beg;
    for (; p + 8 <= end; p += 8) {         // 4 edges per half-warp
        int o0 = __ldg(&g_esrc[p     + half_id]);
        int o1 = __ldg(&g_esrc[p + 2 + half_id]);
        int o2 = __ldg(&g_esrc[p + 4 + half_id]);
        int o3 = __ldg(&g_esrc[p + 6 + half_id]);
        uint2 a = *(const uint2*)(Y + o0 + qb);
        uint2 c = *(const uint2*)(Y + o1 + qb);
        uint2 d = *(const uint2*)(Y + o2 + qb);
        uint2 e = *(const uint2*)(Y + o3 + qb);
        m01 = __hmax2(m01, __hmax2(__hmax2(*(__half2*)&a.x, *(__half2*)&c.x),
                                   __hmax2(*(__half2*)&d.x, *(__half2*)&e.x)));
        m23 = __hmax2(m23, __hmax2(__hmax2(*(__half2*)&a.y, *(__half2*)&c.y),
                                   __hmax2(*(__half2*)&d.y, *(__half2*)&e.y)));
    }
    if (p + 4 <= end) {                    // 2 edges per half-warp
        int o0 = __ldg(&g_esrc[p     + half_id]);
        int o1 = __ldg(&g_esrc[p + 2 + half_id]);
        uint2 a = *(const uint2*)(Y + o0 + qb);
        uint2 c = *(const uint2*)(Y + o1 + qb);
        m01 = __hmax2(m01, __hmax2(*(__half2*)&a.x, *(__half2*)&c.x));
        m23 = __hmax2(m23, __hmax2(*(__half2*)&a.y, *(__half2*)&c.y));
        p += 4;
    }
    for (; p < end; p++) {                 // tail: both halves duplicate
        int o = __ldg(&g_esrc[p]);
        uint2 a = *(const uint2*)(Y + o + qb);
        m01 = __hmax2(m01, *(__half2*)&a.x);
        m23 = __hmax2(m23, *(__half2*)&a.y);
    }
    unsigned u01 = *(unsigned*)&m01, u23 = *(unsigned*)&m23;
    unsigned o01 = __shfl_xor_sync(0xffffffffu, u01, 16);
    unsigned o23 = __shfl_xor_sync(0xffffffffu, u23, 16);
    m01 = __hmax2(m01, *(__half2*)&o01);
    m23 = __hmax2(m23, *(__half2*)&o23);
}

// agg[i] = max_{src} yh[src] - yh[i]  (0 for isolated nodes)
__global__ void agg_kernel(const __half* __restrict__ yh,
                           float* __restrict__ out, int N) {
    int wid = (blockIdx.x * blockDim.x + threadIdx.x) >> 5;
    int lane = threadIdx.x & 31;
    if (wid >= N) return;
    int beg = g_rowptr[wid];
    int end = g_rowptr[wid + 1];
    __half2 m01, m23;
    agg_core_h(yh, beg, end, lane, m01, m23);
    if (lane < 16) {
        int q = lane;
        float4 o;
        if (beg == end) {
            o = make_float4(0.f, 0.f, 0.f, 0.f);
        } else {
            uint2 sp = *(const uint2*)&yh[(size_t)wid * DD + q * 4];
            float2 f01 = __half22float2(m01);
            float2 f23 = __half22float2(m23);
            float2 s01 = __half22float2(*(__half2*)&sp.x);
            float2 s23 = __half22float2(*(__half2*)&sp.y);
            o.x = f01.x - s01.x; o.y = f01.y - s01.y;
            o.z = f23.x - s23.x; o.w = f23.y - s23.y;
        }
        *(float4*)&out[(size_t)wid * DD + q * 4] = o;
    }
}

// last layer: agg + dot with folded head vector + sigmoid, fused.
__global__ void agg_final_kernel(const __half* __restrict__ yh,
                                 float* __restrict__ out, int N) {
    int wid = (blockIdx.x * blockDim.x + threadIdx.x) >> 5;
    int lane = threadIdx.x & 31;
    if (wid >= N) return;
    int beg = g_rowptr[wid];
    int end = g_rowptr[wid + 1];
    __half2 m01, m23;
    agg_core_h(yh, beg, end, lane, m01, m23);
    int q = lane & 15;
    float p = 0.f;
    if (beg != end) {
        uint2 sp = *(const uint2*)&yh[(size_t)wid * DD + q * 4];
        float2 f01 = __half22float2(m01);
        float2 f23 = __half22float2(m23);
        float2 s01 = __half22float2(*(__half2*)&sp.x);
        float2 s23 = __half22float2(*(__half2*)&sp.y);
        float4 vv = *(const float4*)&g_v[q * 4];
        p = (f01.x - s01.x) * vv.x + (f01.y - s01.y) * vv.y
          + (f23.x - s23.x) * vv.z + (f23.y - s23.y) * vv.w;
    }
#pragma unroll
    for (int off = 8; off; off >>= 1)
        p += __shfl_xor_sync(0xffffffffu, p, off);
    if (lane == 0)
        out[wid] = 1.f / (1.f + expf(-(p + g_bias)));
}

extern "C" void kernel_launch(void* const* d_in, const int* in_sizes, int n_in,
                              void* d_out, int out_size) {
    const float* x     = (const float*)d_in[0];
    const void*  edges = d_in[1];
    const float* Wp    = (const float*)d_in[2];
    const float* Wt    = (const float*)d_in[3];
    const float* Wout  = (const float*)d_in[4];
    const float* bout  = (const float*)d_in[5];
    float* out = (float*)d_out;

    int N = in_sizes[0] / DD;
    int E = in_sizes[1] / 2;

    __half* yhp;
    float *aggp, *m1p, *m2p;
    cudaGetSymbolAddress((void**)&yhp, g_yh);
    cudaGetSymbolAddress((void**)&aggp, g_agg);
    cudaGetSymbolAddress((void**)&m1p, g_M1);
    cudaGetSymbolAddress((void**)&m2p, g_M2);

    const int TB = 256;
    int ebl = (E + TB - 1) / TB;
    int wbl = ((N * 32) + TB - 1) / TB;   // warp-per-node grids
    int gbl = (N + 31) / 32;              // 32-row GEMM tiles

    hist_kernel<<<ebl, TB>>>(edges, E);
    scan_fused<<<SCB, 256>>>(Wp, Wt, Wout, bout, N);
    scatter_kernel<<<ebl, TB>>>(edges, E);

    // layer 0
    gemm_kernel<<<gbl, 256>>>(x, Wp, yhp, N);
    agg_kernel<<<wbl, TB>>>(yhp, aggp, N);
    // layer 1
    gemm_kernel<<<gbl, 256>>>(aggp, m1p, yhp, N);
    agg_kernel<<<wbl, TB>>>(yhp, aggp, N);
    // layer 2 + head
    gemm_kernel<<<gbl, 256>>>(aggp, m2p, yhp, N);
    agg_final_kernel<<<wbl, TB>>>(yhp, out, N);
}

// round 11
// speedup vs baseline: 1.1524x; 1.1524x over previous
#include <cuda_runtime.h>
#include <cuda_fp16.h>
#include <math.h>
#include <stdint.h>

#define NMAX 100000
#define EMAX 1600000
#define DD 64
#define SCB 200          // scan blocks; 200*512 = 102400 >= NMAX; co-resident

typedef unsigned long long u64;

// ---------------- device scratch (no allocations allowed) ----------------
__device__ int    g_counts[NMAX];        // zeroed by scan_fused after use
__device__ int    g_fill[NMAX];
__device__ int    g_rowptr[NMAX + 1];
__device__ int    g_esrc[EMAX];          // BYTE offsets: src * 128
__device__ int    g_bsum[SCB];
__device__ unsigned long long g_barctr;  // monotonic, never reset (replay-safe)
__device__ __half g_yh[(size_t)NMAX * DD];
__device__ float  g_agg[(size_t)NMAX * DD];
__device__ float  g_M1[DD * DD];
__device__ float  g_M2[DD * DD];
__device__ float  g_v[DD];
__device__ float  g_bias;

// inline edge-dtype detect: warp 0 ballots 32 odd words (int64 => all zero)
__device__ __forceinline__ int detect_is64_block(const void* edges, int* s64) {
    if (threadIdx.x < 32) {
        const int* w = (const int*)edges;
        int v = w[2 * threadIdx.x + 1];
        unsigned nz = __ballot_sync(0xffffffffu, v != 0);
        if (threadIdx.x == 0) *s64 = (nz == 0u) ? 1 : 0;
    }
    __syncthreads();
    return *s64;
}

__global__ void hist_kernel(const void* __restrict__ edges, int E) {
    __shared__ int s64;
    int is64 = detect_is64_block(edges, &s64);
    int e = blockIdx.x * blockDim.x + threadIdx.x;
    if (e >= E) return;
    int dst;
    if (is64) dst = (int)((const long long*)edges)[E + e];
    else      dst = ((const int*)edges)[E + e];
    atomicAdd(&g_counts[dst], 1);
}

// ---------------- fused: matprep + single-kernel scan ---------------------
__device__ __forceinline__ void grid_barrier_200() {
    __syncthreads();
    if (threadIdx.x == 0) {
        __threadfence();
        unsigned long long my = atomicAdd(&g_barctr, 1ULL) + 1ULL;
        unsigned long long target = ((my + SCB - 1) / SCB) * (unsigned long long)SCB;
        while (atomicAdd(&g_barctr, 0ULL) < target) { }
        __threadfence();
    }
    __syncthreads();
}

__global__ void scan_fused(const float* __restrict__ Wp,
                           const float* __restrict__ Wt,
                           const float* __restrict__ Wout,
                           const float* __restrict__ bout, int N) {
    int b = blockIdx.x, t = threadIdx.x;

    // ---- matprep on blocks 0..15 (4096 lanes) ----
    if (b < 16) {
        int id = b * 256 + t;
        int i = id >> 6, k = id & 63;
        float s1 = 0.f, s2 = 0.f;
#pragma unroll
        for (int m = 0; m < DD; m++) {
            s1 += Wp[1 * DD * DD + i * DD + m] * Wt[0 * DD * DD + m * DD + k];
            s2 += Wp[2 * DD * DD + i * DD + m] * Wt[1 * DD * DD + m * DD + k];
        }
        g_M1[id] = s1;
        g_M2[id] = s2;
        if (i == 0) {
            float sv = 0.f;
#pragma unroll
            for (int m = 0; m < DD; m++)
                sv += Wout[m] * Wt[2 * DD * DD + m * DD + k];
            g_v[k] = sv;
        }
        if (id == 0) g_bias = bout[0];
    }

    // ---- phase 1: block sum over its 512-element chunk ----
    __shared__ int sm[256];
    int base = b * 512 + t * 2;
    int c0 = (base < N) ? g_counts[base] : 0;
    int c1 = (base + 1 < N) ? g_counts[base + 1] : 0;
    int s = c0 + c1;
    sm[t] = s;
    __syncthreads();
    for (int off = 128; off; off >>= 1) {
        if (t < off) sm[t] += sm[t + off];
        __syncthreads();
    }
    if (t == 0) g_bsum[b] = sm[0];

    grid_barrier_200();

    // ---- phase 2a: block offset = exclusive prefix of g_bsum ----
    __shared__ int sb[256];
    sb[t] = (t < SCB) ? g_bsum[t] : 0;
    __syncthreads();
    for (int off = 1; off < 256; off <<= 1) {
        int v = (t >= off) ? sb[t - off] : 0;
        __syncthreads();
        sb[t] += v;
        __syncthreads();
    }
    int blockoff = (b == 0) ? 0 : sb[b - 1];
    if (b == SCB - 1 && t == 0) g_rowptr[N] = sb[SCB - 1];

    // ---- phase 2b: local exclusive scan + write + zero counts ----
    sm[t] = s;
    __syncthreads();
    for (int off = 1; off < 256; off <<= 1) {
        int v = (t >= off) ? sm[t - off] : 0;
        __syncthreads();
        sm[t] += v;
        __syncthreads();
    }
    int pre = sm[t] - s + blockoff;
    if (base < N)     { g_rowptr[base] = pre;          g_fill[base] = pre;          g_counts[base] = 0; }
    if (base + 1 < N) { g_rowptr[base + 1] = pre + c0; g_fill[base + 1] = pre + c0; g_counts[base + 1] = 0; }
}

__global__ void scatter_kernel(const void* __restrict__ edges, int E) {
    __shared__ int s64;
    int is64 = detect_is64_block(edges, &s64);
    int e = blockIdx.x * blockDim.x + threadIdx.x;
    if (e >= E) return;
    int src, dst;
    if (is64) {
        const long long* p = (const long long*)edges;
        src = (int)p[e]; dst = (int)p[E + e];
    } else {
        const int* p = (const int*)edges;
        src = p[e]; dst = p[E + e];
    }
    int pos = atomicAdd(&g_fill[dst], 1);
    g_esrc[pos] = src << 7;              // byte offset into fp16 rows (64*2B)
}

// ---------------- GEMM: fat-microtile FFMA2 -------------------------------
// 128 threads, tile 64 rows x 64 cols, thread = 4 rows x 8 cols.
// Per k-chunk (4 k): 4 A LDS.128 + 8 B LDS.128->u64-pairs = 12 LDS : 64 FFMA2.
// sMt (M transposed, stride 68) + sx (stride 68) = 34.8 kB smem.
#define SXS 68
__global__ void gemm_kernel(const float* __restrict__ x,
                            const float* __restrict__ M,
                            __half* __restrict__ out, int N) {
    __shared__ float sx[DD][SXS];
    __shared__ float sMt[DD][SXS];   // sMt[k][col] = M[col][k]
    int t = threadIdx.x;
    int base = blockIdx.x * DD;

    // stage: 1024 float4 each, 8 per thread
#pragma unroll
    for (int i = 0; i < 8; i++) {
        int v = t + 128 * i;          // float4 index in [0,1024)
        int r = v >> 4;
        int c4 = (v & 15) * 4;
        float4 mv = *(const float4*)&M[r * DD + c4];
        sMt[c4][r] = mv.x; sMt[c4 + 1][r] = mv.y;
        sMt[c4 + 2][r] = mv.z; sMt[c4 + 3][r] = mv.w;
        float4 xv = make_float4(0.f, 0.f, 0.f, 0.f);
        if (base + r < N)
            xv = *(const float4*)&x[(size_t)(base + r) * DD + c4];
        *(float4*)&sx[r][c4] = xv;
    }
    __syncthreads();

    int cg = t & 7;                  // col group: cols cg*8 .. cg*8+7
    int rg = t >> 3;                 // row group: rows rg*4 .. rg*4+3
    int tc = cg * 8;
    int r0 = rg * 4;

    u64 acc2[4][4];                  // [row][col-pair]
#pragma unroll
    for (int i = 0; i < 4; i++)
#pragma unroll
        for (int j = 0; j < 4; j++) acc2[i][j] = 0ULL;

#pragma unroll
    for (int k = 0; k < DD; k += 4) {
        // A: 4 rows x 4 k  (4 LDS.128)
        float4 a0 = *(const float4*)&sx[r0    ][k];
        float4 a1 = *(const float4*)&sx[r0 + 1][k];
        float4 a2 = *(const float4*)&sx[r0 + 2][k];
        float4 a3 = *(const float4*)&sx[r0 + 3][k];
#pragma unroll
        for (int kk = 0; kk < 4; kk++) {
            // B: 8 cols for this k  (2 LDS.128 -> 4 u64 pairs)
            float4 blo = *(const float4*)&sMt[k + kk][tc];
            float4 bhi = *(const float4*)&sMt[k + kk][tc + 4];
            u64 b0 = *(const u64*)&blo.x;
            u64 b1 = *(const u64*)&blo.z;
            u64 b2 = *(const u64*)&bhi.x;
            u64 b3 = *(const u64*)&bhi.z;
            float v0 = (kk == 0) ? a0.x : (kk == 1) ? a0.y : (kk == 2) ? a0.z : a0.w;
            float v1 = (kk == 0) ? a1.x : (kk == 1) ? a1.y : (kk == 2) ? a1.z : a1.w;
            float v2 = (kk == 0) ? a2.x : (kk == 1) ? a2.y : (kk == 2) ? a2.z : a2.w;
            float v3 = (kk == 0) ? a3.x : (kk == 1) ? a3.y : (kk == 2) ? a3.z : a3.w;
            u64 aa;
            asm("mov.b64 %0, {%1, %1};" : "=l"(aa) : "f"(v0));
            asm("fma.rn.f32x2 %0, %1, %2, %0;" : "+l"(acc2[0][0]) : "l"(aa), "l"(b0));
            asm("fma.rn.f32x2 %0, %1, %2, %0;" : "+l"(acc2[0][1]) : "l"(aa), "l"(b1));
            asm("fma.rn.f32x2 %0, %1, %2, %0;" : "+l"(acc2[0][2]) : "l"(aa), "l"(b2));
            asm("fma.rn.f32x2 %0, %1, %2, %0;" : "+l"(acc2[0][3]) : "l"(aa), "l"(b3));
            asm("mov.b64 %0, {%1, %1};" : "=l"(aa) : "f"(v1));
            asm("fma.rn.f32x2 %0, %1, %2, %0;" : "+l"(acc2[1][0]) : "l"(aa), "l"(b0));
            asm("fma.rn.f32x2 %0, %1, %2, %0;" : "+l"(acc2[1][1]) : "l"(aa), "l"(b1));
            asm("fma.rn.f32x2 %0, %1, %2, %0;" : "+l"(acc2[1][2]) : "l"(aa), "l"(b2));
            asm("fma.rn.f32x2 %0, %1, %2, %0;" : "+l"(acc2[1][3]) : "l"(aa), "l"(b3));
            asm("mov.b64 %0, {%1, %1};" : "=l"(aa) : "f"(v2));
            asm("fma.rn.f32x2 %0, %1, %2, %0;" : "+l"(acc2[2][0]) : "l"(aa), "l"(b0));
            asm("fma.rn.f32x2 %0, %1, %2, %0;" : "+l"(acc2[2][1]) : "l"(aa), "l"(b1));
            asm("fma.rn.f32x2 %0, %1, %2, %0;" : "+l"(acc2[2][2]) : "l"(aa), "l"(b2));
            asm("fma.rn.f32x2 %0, %1, %2, %0;" : "+l"(acc2[2][3]) : "l"(aa), "l"(b3));
            asm("mov.b64 %0, {%1, %1};" : "=l"(aa) : "f"(v3));
            asm("fma.rn.f32x2 %0, %1, %2, %0;" : "+l"(acc2[3][0]) : "l"(aa), "l"(b0));
            asm("fma.rn.f32x2 %0, %1, %2, %0;" : "+l"(acc2[3][1]) : "l"(aa), "l"(b1));
            asm("fma.rn.f32x2 %0, %1, %2, %0;" : "+l"(acc2[3][2]) : "l"(aa), "l"(b2));
            asm("fma.rn.f32x2 %0, %1, %2, %0;" : "+l"(acc2[3][3]) : "l"(aa), "l"(b3));
        }
    }

#pragma unroll
    for (int i = 0; i < 4; i++) {
        int row = base + r0 + i;
        if (row < N) {
            float c0, c1, c2, c3, c4, c5, c6, c7;
            asm("mov.b64 {%0, %1}, %2;" : "=f"(c0), "=f"(c1) : "l"(acc2[i][0]));
            asm("mov.b64 {%0, %1}, %2;" : "=f"(c2), "=f"(c3) : "l"(acc2[i][1]));
            asm("mov.b64 {%0, %1}, %2;" : "=f"(c4), "=f"(c5) : "l"(acc2[i][2]));
            asm("mov.b64 {%0, %1}, %2;" : "=f"(c6), "=f"(c7) : "l"(acc2[i][3]));
            __half2 h0 = __floats2half2_rn(c0, c1);
            __half2 h1 = __floats2half2_rn(c2, c3);
            __half2 h2 = __floats2half2_rn(c4, c5);
            __half2 h3 = __floats2half2_rn(c6, c7);
            uint4 pack;
            pack.x = *(const unsigned*)&h0;
            pack.y = *(const unsigned*)&h1;
            pack.z = *(const unsigned*)&h2;
            pack.w = *(const unsigned*)&h3;
            *(uint4*)&out[(size_t)row * DD + tc] = pack;
        }
    }
}

// ---------------- aggregation core (fp16 gather, uniform-ldg indices) -----
__device__ __forceinline__ void agg_core_h(const __half* __restrict__ yh,
                                           int beg, int end, int lane,
                                           __half2& m01, __half2& m23) {
    const __half2 ninf = __float2half2_rn(-INFINITY);
    m01 = ninf; m23 = ninf;
    const char* Y = (const char*)yh;
    int half_id = lane >> 4;
    int qb = (lane & 15) * 8;
    int p = beg;
    for (; p + 8 <= end; p += 8) {         // 4 edges per half-warp
        int o0 = __ldg(&g_esrc[p     + half_id]);
        int o1 = __ldg(&g_esrc[p + 2 + half_id]);
        int o2 = __ldg(&g_esrc[p + 4 + half_id]);
        int o3 = __ldg(&g_esrc[p + 6 + half_id]);
        uint2 a = *(const uint2*)(Y + o0 + qb);
        uint2 c = *(const uint2*)(Y + o1 + qb);
        uint2 d = *(const uint2*)(Y + o2 + qb);
        uint2 e = *(const uint2*)(Y + o3 + qb);
        m01 = __hmax2(m01, __hmax2(__hmax2(*(__half2*)&a.x, *(__half2*)&c.x),
                                   __hmax2(*(__half2*)&d.x, *(__half2*)&e.x)));
        m23 = __hmax2(m23, __hmax2(__hmax2(*(__half2*)&a.y, *(__half2*)&c.y),
                                   __hmax2(*(__half2*)&d.y, *(__half2*)&e.y)));
    }
    if (p + 4 <= end) {                    // 2 edges per half-warp
        int o0 = __ldg(&g_esrc[p     + half_id]);
        int o1 = __ldg(&g_esrc[p + 2 + half_id]);
        uint2 a = *(const uint2*)(Y + o0 + qb);
        uint2 c = *(const uint2*)(Y + o1 + qb);
        m01 = __hmax2(m01, __hmax2(*(__half2*)&a.x, *(__half2*)&c.x));
        m23 = __hmax2(m23, __hmax2(*(__half2*)&a.y, *(__half2*)&c.y));
        p += 4;
    }
    for (; p < end; p++) {                 // tail: both halves duplicate
        int o = __ldg(&g_esrc[p]);
        uint2 a = *(const uint2*)(Y + o + qb);
        m01 = __hmax2(m01, *(__half2*)&a.x);
        m23 = __hmax2(m23, *(__half2*)&a.y);
    }
    unsigned u01 = *(unsigned*)&m01, u23 = *(unsigned*)&m23;
    unsigned o01 = __shfl_xor_sync(0xffffffffu, u01, 16);
    unsigned o23 = __shfl_xor_sync(0xffffffffu, u23, 16);
    m01 = __hmax2(m01, *(__half2*)&o01);
    m23 = __hmax2(m23, *(__half2*)&o23);
}

// agg[i] = max_{src} yh[src] - yh[i]  (0 for isolated nodes)
__global__ void agg_kernel(const __half* __restrict__ yh,
                           float* __restrict__ out, int N) {
    int wid = (blockIdx.x * blockDim.x + threadIdx.x) >> 5;
    int lane = threadIdx.x & 31;
    if (wid >= N) return;
    int beg = g_rowptr[wid];
    int end = g_rowptr[wid + 1];
    __half2 m01, m23;
    agg_core_h(yh, beg, end, lane, m01, m23);
    if (lane < 16) {
        int q = lane;
        float4 o;
        if (beg == end) {
            o = make_float4(0.f, 0.f, 0.f, 0.f);
        } else {
            uint2 sp = *(const uint2*)&yh[(size_t)wid * DD + q * 4];
            float2 f01 = __half22float2(m01);
            float2 f23 = __half22float2(m23);
            float2 s01 = __half22float2(*(__half2*)&sp.x);
            float2 s23 = __half22float2(*(__half2*)&sp.y);
            o.x = f01.x - s01.x; o.y = f01.y - s01.y;
            o.z = f23.x - s23.x; o.w = f23.y - s23.y;
        }
        *(float4*)&out[(size_t)wid * DD + q * 4] = o;
    }
}

// last layer: agg + dot with folded head vector + sigmoid, fused.
__global__ void agg_final_kernel(const __half* __restrict__ yh,
                                 float* __restrict__ out, int N) {
    int wid = (blockIdx.x * blockDim.x + threadIdx.x) >> 5;
    int lane = threadIdx.x & 31;
    if (wid >= N) return;
    int beg = g_rowptr[wid];
    int end = g_rowptr[wid + 1];
    __half2 m01, m23;
    agg_core_h(yh, beg, end, lane, m01, m23);
    int q = lane & 15;
    float p = 0.f;
    if (beg != end) {
        uint2 sp = *(const uint2*)&yh[(size_t)wid * DD + q * 4];
        float2 f01 = __half22float2(m01);
        float2 f23 = __half22float2(m23);
        float2 s01 = __half22float2(*(__half2*)&sp.x);
        float2 s23 = __half22float2(*(__half2*)&sp.y);
        float4 vv = *(const float4*)&g_v[q * 4];
        p = (f01.x - s01.x) * vv.x + (f01.y - s01.y) * vv.y
          + (f23.x - s23.x) * vv.z + (f23.y - s23.y) * vv.w;
    }
#pragma unroll
    for (int off = 8; off; off >>= 1)
        p += __shfl_xor_sync(0xffffffffu, p, off);
    if (lane == 0)
        out[wid] = 1.f / (1.f + expf(-(p + g_bias)));
}

extern "C" void kernel_launch(void* const* d_in, const int* in_sizes, int n_in,
                              void* d_out, int out_size) {
    const float* x     = (const float*)d_in[0];
    const void*  edges = d_in[1];
    const float* Wp    = (const float*)d_in[2];
    const float* Wt    = (const float*)d_in[3];
    const float* Wout  = (const float*)d_in[4];
    const float* bout  = (const float*)d_in[5];
    float* out = (float*)d_out;

    int N = in_sizes[0] / DD;
    int E = in_sizes[1] / 2;

    __half* yhp;
    float *aggp, *m1p, *m2p;
    cudaGetSymbolAddress((void**)&yhp, g_yh);
    cudaGetSymbolAddress((void**)&aggp, g_agg);
    cudaGetSymbolAddress((void**)&m1p, g_M1);
    cudaGetSymbolAddress((void**)&m2p, g_M2);

    const int TB = 256;
    int ebl = (E + TB - 1) / TB;
    int wbl = ((N * 32) + TB - 1) / TB;   // warp-per-node grids
    int gbl = (N + DD - 1) / DD;          // 64-row GEMM tiles

    hist_kernel<<<ebl, TB>>>(edges, E);
    scan_fused<<<SCB, 256>>>(Wp, Wt, Wout, bout, N);
    scatter_kernel<<<ebl, TB>>>(edges, E);

    // layer 0
    gemm_kernel<<<gbl, 128>>>(x, Wp, yhp, N);
    agg_kernel<<<wbl, TB>>>(yhp, aggp, N);
    // layer 1
    gemm_kernel<<<gbl, 128>>>(aggp, m1p, yhp, N);
    agg_kernel<<<wbl, TB>>>(yhp, aggp, N);
    // layer 2 + head
    gemm_kernel<<<gbl, 128>>>(aggp, m2p, yhp, N);
    agg_final_kernel<<<wbl, TB>>>(yhp, out, N);
}

// round 12
// speedup vs baseline: 1.4201x; 1.2323x over previous
#include <cuda_runtime.h>
#include <cuda_fp16.h>
#include <math.h>
#include <stdint.h>

#define NMAX 100000
#define EMAX 1600000
#define DD 64
#define SCB 200          // scan blocks; 200*512 = 102400 >= NMAX; co-resident

typedef unsigned long long u64;

// ---------------- device scratch (no allocations allowed) ----------------
__device__ int    g_counts[NMAX];        // zeroed by scan_fused after use
__device__ int    g_fill[NMAX];
__device__ int    g_rowptr[NMAX + 1];
__device__ int    g_esrc[EMAX];          // BYTE offsets: src * 128
__device__ int    g_bsum[SCB];
__device__ unsigned long long g_barctr;  // monotonic, never reset (replay-safe)
__device__ __half g_yh[(size_t)NMAX * DD];   // fp16 activations (gather)
__device__ __half g_xh[(size_t)NMAX * DD];   // split of layer-0 input (hi)
__device__ __half g_xl[(size_t)NMAX * DD];   // (lo)
__device__ __half g_ah[(size_t)NMAX * DD];   // split agg output (hi)
__device__ __half g_al[(size_t)NMAX * DD];   // (lo)
__device__ __half g_Bh[3 * DD * DD];         // split B matrices: Wp0, M1, M2 (hi)
__device__ __half g_Bl[3 * DD * DD];         // (lo)
__device__ float  g_v[DD];
__device__ float  g_bias;

// inline edge-dtype detect: warp 0 ballots 32 odd words (int64 => all zero)
__device__ __forceinline__ int detect_is64_block(const void* edges, int* s64) {
    if (threadIdx.x < 32) {
        const int* w = (const int*)edges;
        int v = w[2 * threadIdx.x + 1];
        unsigned nz = __ballot_sync(0xffffffffu, v != 0);
        if (threadIdx.x == 0) *s64 = (nz == 0u) ? 1 : 0;
    }
    __syncthreads();
    return *s64;
}

__global__ void hist_kernel(const void* __restrict__ edges, int E) {
    __shared__ int s64;
    int is64 = detect_is64_block(edges, &s64);
    int e = blockIdx.x * blockDim.x + threadIdx.x;
    if (e >= E) return;
    int dst;
    if (is64) dst = (int)((const long long*)edges)[E + e];
    else      dst = ((const int*)edges)[E + e];
    atomicAdd(&g_counts[dst], 1);
}

// ---------------- split helpers ------------------------------------------
__device__ __forceinline__ void split2(float v, __half& h, __half& l) {
    h = __float2half_rn(v);
    l = __float2half_rn(v - __half2float(h));
}

// split x into hi/lo halves (8 floats per thread)
__global__ void splitx_kernel(const float* __restrict__ x, int total) {
    int i = (blockIdx.x * blockDim.x + threadIdx.x) * 8;
    if (i >= total) return;
    float4 f0 = *(const float4*)&x[i];
    float4 f1 = *(const float4*)&x[i + 4];
    __half h[8], l[8];
    split2(f0.x, h[0], l[0]); split2(f0.y, h[1], l[1]);
    split2(f0.z, h[2], l[2]); split2(f0.w, h[3], l[3]);
    split2(f1.x, h[4], l[4]); split2(f1.y, h[5], l[5]);
    split2(f1.z, h[6], l[6]); split2(f1.w, h[7], l[7]);
    *(uint4*)&g_xh[i] = *(const uint4*)h;
    *(uint4*)&g_xl[i] = *(const uint4*)l;
}

// ---------------- fused: matprep(+split) + single-kernel scan -------------
__device__ __forceinline__ void grid_barrier_200() {
    __syncthreads();
    if (threadIdx.x == 0) {
        __threadfence();
        unsigned long long my = atomicAdd(&g_barctr, 1ULL) + 1ULL;
        unsigned long long target = ((my + SCB - 1) / SCB) * (unsigned long long)SCB;
        while (atomicAdd(&g_barctr, 0ULL) < target) { }
        __threadfence();
    }
    __syncthreads();
}

__global__ void scan_fused(const float* __restrict__ Wp,
                           const float* __restrict__ Wt,
                           const float* __restrict__ Wout,
                           const float* __restrict__ bout, int N) {
    int b = blockIdx.x, t = threadIdx.x;

    // ---- matprep on blocks 0..15 (4096 lanes): fold + fp16-split ----
    if (b < 16) {
        int id = b * 256 + t;
        int i = id >> 6, k = id & 63;
        float s1 = 0.f, s2 = 0.f;
#pragma unroll
        for (int m = 0; m < DD; m++) {
            s1 += Wp[1 * DD * DD + i * DD + m] * Wt[0 * DD * DD + m * DD + k];
            s2 += Wp[2 * DD * DD + i * DD + m] * Wt[1 * DD * DD + m * DD + k];
        }
        __half h, l;
        split2(Wp[id], h, l);                 // layer-0 B = Wp0
        g_Bh[id] = h; g_Bl[id] = l;
        split2(s1, h, l);                     // layer-1 B = Wp1*Wt0
        g_Bh[DD * DD + id] = h; g_Bl[DD * DD + id] = l;
        split2(s2, h, l);                     // layer-2 B = Wp2*Wt1
        g_Bh[2 * DD * DD + id] = h; g_Bl[2 * DD * DD + id] = l;
        if (i == 0) {
            float sv = 0.f;
#pragma unroll
            for (int m = 0; m < DD; m++)
                sv += Wout[m] * Wt[2 * DD * DD + m * DD + k];
            g_v[k] = sv;
        }
        if (id == 0) g_bias = bout[0];
    }

    // ---- phase 1: block sum over its 512-element chunk ----
    __shared__ int sm[256];
    int base = b * 512 + t * 2;
    int c0 = (base < N) ? g_counts[base] : 0;
    int c1 = (base + 1 < N) ? g_counts[base + 1] : 0;
    int s = c0 + c1;
    sm[t] = s;
    __syncthreads();
    for (int off = 128; off; off >>= 1) {
        if (t < off) sm[t] += sm[t + off];
        __syncthreads();
    }
    if (t == 0) g_bsum[b] = sm[0];

    grid_barrier_200();

    // ---- phase 2a: block offset = exclusive prefix of g_bsum ----
    __shared__ int sb[256];
    sb[t] = (t < SCB) ? g_bsum[t] : 0;
    __syncthreads();
    for (int off = 1; off < 256; off <<= 1) {
        int v = (t >= off) ? sb[t - off] : 0;
        __syncthreads();
        sb[t] += v;
        __syncthreads();
    }
    int blockoff = (b == 0) ? 0 : sb[b - 1];
    if (b == SCB - 1 && t == 0) g_rowptr[N] = sb[SCB - 1];

    // ---- phase 2b: local exclusive scan + write + zero counts ----
    sm[t] = s;
    __syncthreads();
    for (int off = 1; off < 256; off <<= 1) {
        int v = (t >= off) ? sm[t - off] : 0;
        __syncthreads();
        sm[t] += v;
        __syncthreads();
    }
    int pre = sm[t] - s + blockoff;
    if (base < N)     { g_rowptr[base] = pre;          g_fill[base] = pre;          g_counts[base] = 0; }
    if (base + 1 < N) { g_rowptr[base + 1] = pre + c0; g_fill[base + 1] = pre + c0; g_counts[base + 1] = 0; }
}

__global__ void scatter_kernel(const void* __restrict__ edges, int E) {
    __shared__ int s64;
    int is64 = detect_is64_block(edges, &s64);
    int e = blockIdx.x * blockDim.x + threadIdx.x;
    if (e >= E) return;
    int src, dst;
    if (is64) {
        const long long* p = (const long long*)edges;
        src = (int)p[e]; dst = (int)p[E + e];
    } else {
        const int* p = (const int*)edges;
        src = p[e]; dst = p[E + e];
    }
    int pos = atomicAdd(&g_fill[dst], 1);
    g_esrc[pos] = src << 7;              // byte offset into fp16 rows (64*2B)
}

// ---------------- GEMM: tensor-core split-fp16 ----------------------------
// out[row][n] = sum_k A[row][k] * B[n][k], A = Ah+Al, B = Bh+Bl (fp16 pairs).
// D = Ah*Bh + Ah*Bl + Al*Bh (3x mma.m16n8k16, fp32 accum) ~ fp32 precision.
// Block: 128 thr = 4 warps; tile 64 rows x 64 cols; warp = 16 rows x 64 cols.
// smem stride 72 halves -> fragment LDS.32 banks == lane id (conflict-free).
#define BST 72
#define MMA16816(c, a0, a1, a2, a3, b0, b1) \
    asm("mma.sync.aligned.m16n8k16.row.col.f32.f16.f16.f32 " \
        "{%0,%1,%2,%3}, {%4,%5,%6,%7}, {%8,%9}, {%0,%1,%2,%3};" \
        : "+f"(c[0]), "+f"(c[1]), "+f"(c[2]), "+f"(c[3]) \
        : "r"(a0), "r"(a1), "r"(a2), "r"(a3), "r"(b0), "r"(b1))

__global__ void __launch_bounds__(128)
gemm_tc(const __half* __restrict__ Ah, const __half* __restrict__ Al,
        const __half* __restrict__ Bh, const __half* __restrict__ Bl,
        __half* __restrict__ out, int N) {
    __shared__ __half sAh[DD][BST], sAl[DD][BST];
    __shared__ __half sBh[DD][BST], sBl[DD][BST];
    int t = threadIdx.x;
    int base = blockIdx.x * DD;

    // stage 4 arrays: 64 rows x 8 uint4 each = 512 uint4/array, 16 per thread.
    // 8-lane phases each fill one full row -> conflict-free STS.128.
#pragma unroll
    for (int i = 0; i < 16; i++) {
        int v = t + 128 * i;
        int arr = v >> 9;
        int v2 = v & 511;
        int row = v2 >> 3;
        int c = (v2 & 7) * 8;
        uint4 val = make_uint4(0u, 0u, 0u, 0u);
        __half* dst;
        if (arr == 0) {
            if (base + row < N) val = *(const uint4*)&Ah[(size_t)(base + row) * DD + c];
            dst = &sAh[row][c];
        } else if (arr == 1) {
            if (base + row < N) val = *(const uint4*)&Al[(size_t)(base + row) * DD + c];
            dst = &sAl[row][c];
        } else if (arr == 2) {
            val = *(const uint4*)&Bh[row * DD + c];
            dst = &sBh[row][c];
        } else {
            val = *(const uint4*)&Bl[row * DD + c];
            dst = &sBl[row][c];
        }
        *(uint4*)dst = val;
    }
    __syncthreads();

    int w = t >> 5, lane = t & 31;
    int rA = 16 * w + (lane >> 2);       // fragment rows rA, rA+8
    int kq = (lane & 3) * 2;             // fragment k-pair base
    int nq = lane >> 2;                  // fragment n within n-block

    float c[8][4];
#pragma unroll
    for (int nb = 0; nb < 8; nb++)
#pragma unroll
        for (int j = 0; j < 4; j++) c[nb][j] = 0.f;

#pragma unroll
    for (int kb = 0; kb < 4; kb++) {
        int k0 = kb * 16 + kq;
        unsigned ah0 = *(const unsigned*)&sAh[rA    ][k0];
        unsigned ah1 = *(const unsigned*)&sAh[rA + 8][k0];
        unsigned ah2 = *(const unsigned*)&sAh[rA    ][k0 + 8];
        unsigned ah3 = *(const unsigned*)&sAh[rA + 8][k0 + 8];
        unsigned al0 = *(const unsigned*)&sAl[rA    ][k0];
        unsigned al1 = *(const unsigned*)&sAl[rA + 8][k0];
        unsigned al2 = *(const unsigned*)&sAl[rA    ][k0 + 8];
        unsigned al3 = *(const unsigned*)&sAl[rA + 8][k0 + 8];
#pragma unroll
        for (int nb = 0; nb < 8; nb++) {
            int nr = nb * 8 + nq;
            unsigned bh0 = *(const unsigned*)&sBh[nr][k0];
            unsigned bh1 = *(const unsigned*)&sBh[nr][k0 + 8];
            unsigned bl0 = *(const unsigned*)&sBl[nr][k0];
            unsigned bl1 = *(const unsigned*)&sBl[nr][k0 + 8];
            MMA16816(c[nb], ah0, ah1, ah2, ah3, bh0, bh1);   // hi*hi
            MMA16816(c[nb], ah0, ah1, ah2, ah3, bl0, bl1);   // hi*lo
            MMA16816(c[nb], al0, al1, al2, al3, bh0, bh1);   // lo*hi
        }
    }

    // epilogue: lane holds D[rA][n0,n0+1] (c0,c1) and D[rA+8][..] (c2,c3)
    int row0 = base + rA;
    int row1 = row0 + 8;
    int ncol = (lane & 3) * 2;
#pragma unroll
    for (int nb = 0; nb < 8; nb++) {
        if (row0 < N) {
            __half2 h = __floats2half2_rn(c[nb][0], c[nb][1]);
            *(unsigned*)&out[(size_t)row0 * DD + nb * 8 + ncol] = *(const unsigned*)&h;
        }
        if (row1 < N) {
            __half2 h = __floats2half2_rn(c[nb][2], c[nb][3]);
            *(unsigned*)&out[(size_t)row1 * DD + nb * 8 + ncol] = *(const unsigned*)&h;
        }
    }
}

// ---------------- aggregation core (fp16 gather, uniform-ldg indices) -----
__device__ __forceinline__ void agg_core_h(const __half* __restrict__ yh,
                                           int beg, int end, int lane,
                                           __half2& m01, __half2& m23) {
    const __half2 ninf = __float2half2_rn(-INFINITY);
    m01 = ninf; m23 = ninf;
    const char* Y = (const char*)yh;
    int half_id = lane >> 4;
    int qb = (lane & 15) * 8;
    int p = beg;
    for (; p + 8 <= end; p += 8) {         // 4 edges per half-warp
        int o0 = __ldg(&g_esrc[p     + half_id]);
        int o1 = __ldg(&g_esrc[p + 2 + half_id]);
        int o2 = __ldg(&g_esrc[p + 4 + half_id]);
        int o3 = __ldg(&g_esrc[p + 6 + half_id]);
        uint2 a = *(const uint2*)(Y + o0 + qb);
        uint2 c = *(const uint2*)(Y + o1 + qb);
        uint2 d = *(const uint2*)(Y + o2 + qb);
        uint2 e = *(const uint2*)(Y + o3 + qb);
        m01 = __hmax2(m01, __hmax2(__hmax2(*(__half2*)&a.x, *(__half2*)&c.x),
                                   __hmax2(*(__half2*)&d.x, *(__half2*)&e.x)));
        m23 = __hmax2(m23, __hmax2(__hmax2(*(__half2*)&a.y, *(__half2*)&c.y),
                                   __hmax2(*(__half2*)&d.y, *(__half2*)&e.y)));
    }
    if (p + 4 <= end) {                    // 2 edges per half-warp
        int o0 = __ldg(&g_esrc[p     + half_id]);
        int o1 = __ldg(&g_esrc[p + 2 + half_id]);
        uint2 a = *(const uint2*)(Y + o0 + qb);
        uint2 c = *(const uint2*)(Y + o1 + qb);
        m01 = __hmax2(m01, __hmax2(*(__half2*)&a.x, *(__half2*)&c.x));
        m23 = __hmax2(m23, __hmax2(*(__half2*)&a.y, *(__half2*)&c.y));
        p += 4;
    }
    for (; p < end; p++) {                 // tail: both halves duplicate
        int o = __ldg(&g_esrc[p]);
        uint2 a = *(const uint2*)(Y + o + qb);
        m01 = __hmax2(m01, *(__half2*)&a.x);
        m23 = __hmax2(m23, *(__half2*)&a.y);
    }
    unsigned u01 = *(unsigned*)&m01, u23 = *(unsigned*)&m23;
    unsigned o01 = __shfl_xor_sync(0xffffffffu, u01, 16);
    unsigned o23 = __shfl_xor_sync(0xffffffffu, u23, 16);
    m01 = __hmax2(m01, *(__half2*)&o01);
    m23 = __hmax2(m23, *(__half2*)&o23);
}

// agg: out = split( max_{src} yh[src] - yh[i] )  into g_ah/g_al
__global__ void agg_kernel(const __half* __restrict__ yh, int N) {
    int wid = (blockIdx.x * blockDim.x + threadIdx.x) >> 5;
    int lane = threadIdx.x & 31;
    if (wid >= N) return;
    int beg = g_rowptr[wid];
    int end = g_rowptr[wid + 1];
    __half2 m01, m23;
    agg_core_h(yh, beg, end, lane, m01, m23);
    if (lane < 16) {
        int q = lane;
        float d0 = 0.f, d1 = 0.f, d2 = 0.f, d3 = 0.f;
        if (beg != end) {
            uint2 sp = *(const uint2*)&yh[(size_t)wid * DD + q * 4];
            float2 f01 = __half22float2(m01);
            float2 f23 = __half22float2(m23);
            float2 s01 = __half22float2(*(__half2*)&sp.x);
            float2 s23 = __half22float2(*(__half2*)&sp.y);
            d0 = f01.x - s01.x; d1 = f01.y - s01.y;
            d2 = f23.x - s23.x; d3 = f23.y - s23.y;
        }
        __half h0, l0, h1, l1, h2, l2, h3, l3;
        split2(d0, h0, l0); split2(d1, h1, l1);
        split2(d2, h2, l2); split2(d3, h3, l3);
        __half hv[4] = {h0, h1, h2, h3};
        __half lv[4] = {l0, l1, l2, l3};
        *(uint2*)&g_ah[(size_t)wid * DD + q * 4] = *(const uint2*)hv;
        *(uint2*)&g_al[(size_t)wid * DD + q * 4] = *(const uint2*)lv;
    }
}

// last layer: agg + dot with folded head vector + sigmoid, fused.
__global__ void agg_final_kernel(const __half* __restrict__ yh,
                                 float* __restrict__ out, int N) {
    int wid = (blockIdx.x * blockDim.x + threadIdx.x) >> 5;
    int lane = threadIdx.x & 31;
    if (wid >= N) return;
    int beg = g_rowptr[wid];
    int end = g_rowptr[wid + 1];
    __half2 m01, m23;
    agg_core_h(yh, beg, end, lane, m01, m23);
    int q = lane & 15;
    float p = 0.f;
    if (beg != end) {
        uint2 sp = *(const uint2*)&yh[(size_t)wid * DD + q * 4];
        float2 f01 = __half22float2(m01);
        float2 f23 = __half22float2(m23);
        float2 s01 = __half22float2(*(__half2*)&sp.x);
        float2 s23 = __half22float2(*(__half2*)&sp.y);
        float4 vv = *(const float4*)&g_v[q * 4];
        p = (f01.x - s01.x) * vv.x + (f01.y - s01.y) * vv.y
          + (f23.x - s23.x) * vv.z + (f23.y - s23.y) * vv.w;
    }
#pragma unroll
    for (int off = 8; off; off >>= 1)
        p += __shfl_xor_sync(0xffffffffu, p, off);
    if (lane == 0)
        out[wid] = 1.f / (1.f + expf(-(p + g_bias)));
}

extern "C" void kernel_launch(void* const* d_in, const int* in_sizes, int n_in,
                              void* d_out, int out_size) {
    const float* x     = (const float*)d_in[0];
    const void*  edges = d_in[1];
    const float* Wp    = (const float*)d_in[2];
    const float* Wt    = (const float*)d_in[3];
    const float* Wout  = (const float*)d_in[4];
    const float* bout  = (const float*)d_in[5];
    float* out = (float*)d_out;

    int N = in_sizes[0] / DD;
    int E = in_sizes[1] / 2;

    __half *yhp, *xhp, *xlp, *ahp, *alp, *bhp, *blp;
    cudaGetSymbolAddress((void**)&yhp, g_yh);
    cudaGetSymbolAddress((void**)&xhp, g_xh);
    cudaGetSymbolAddress((void**)&xlp, g_xl);
    cudaGetSymbolAddress((void**)&ahp, g_ah);
    cudaGetSymbolAddress((void**)&alp, g_al);
    cudaGetSymbolAddress((void**)&bhp, g_Bh);
    cudaGetSymbolAddress((void**)&blp, g_Bl);

    const int TB = 256;
    int ebl = (E + TB - 1) / TB;
    int wbl = ((N * 32) + TB - 1) / TB;   // warp-per-node grids
    int gbl = (N + DD - 1) / DD;          // 64-row GEMM tiles
    int total = N * DD;
    int sbl = (total / 8 + TB - 1) / TB;  // splitx grid

    hist_kernel<<<ebl, TB>>>(edges, E);
    scan_fused<<<SCB, 256>>>(Wp, Wt, Wout, bout, N);
    scatter_kernel<<<ebl, TB>>>(edges, E);
    splitx_kernel<<<sbl, TB>>>(x, total);

    // layer 0: yh = (x) @ Wp0^T
    gemm_tc<<<gbl, 128>>>(xhp, xlp, bhp, blp, yhp, N);
    agg_kernel<<<wbl, TB>>>(yhp, N);
    // layer 1: yh = agg @ (Wp1 Wt0)^T
    gemm_tc<<<gbl, 128>>>(ahp, alp, bhp + DD * DD, blp + DD * DD, yhp, N);
    agg_kernel<<<wbl, TB>>>(yhp, N);
    // layer 2 + head
    gemm_tc<<<gbl, 128>>>(ahp, alp, bhp + 2 * DD * DD, blp + 2 * DD * DD, yhp, N);
    agg_final_kernel<<<wbl, TB>>>(yhp, out, N);
}

// round 13
// speedup vs baseline: 1.4797x; 1.0419x over previous
#include <cuda_runtime.h>
#include <cuda_fp16.h>
#include <math.h>
#include <stdint.h>

#define NMAX 100000
#define EMAX 1600000
#define DD 64
#define SCB 200          // scan blocks; 200*512 = 102400 >= NMAX; co-resident

typedef unsigned long long u64;

// ---------------- device scratch (no allocations allowed) ----------------
__device__ int    g_counts[NMAX];        // zeroed by scan_fused after use
__device__ int    g_fill[NMAX];
__device__ int    g_rowptr[NMAX + 1];
__device__ int    g_esrc[EMAX];          // BYTE offsets: src * 128
__device__ int    g_bsum[SCB];
__device__ unsigned long long g_barctr;  // monotonic, never reset (replay-safe)
__device__ __half g_yh[(size_t)NMAX * DD];   // fp16 activations (gather)
__device__ __half g_ah[(size_t)NMAX * DD];   // split agg output (hi)
__device__ __half g_al[(size_t)NMAX * DD];   // (lo)
__device__ __half g_Bh[2 * DD * DD];         // split folded B: M1, M2 (hi)
__device__ __half g_Bl[2 * DD * DD];         // (lo)
__device__ float  g_v[DD];
__device__ float  g_bias;

// inline edge-dtype detect: warp 0 ballots 32 odd words (int64 => all zero)
__device__ __forceinline__ int detect_is64_block(const void* edges, int* s64) {
    if (threadIdx.x < 32) {
        const int* w = (const int*)edges;
        int v = w[2 * threadIdx.x + 1];
        unsigned nz = __ballot_sync(0xffffffffu, v != 0);
        if (threadIdx.x == 0) *s64 = (nz == 0u) ? 1 : 0;
    }
    __syncthreads();
    return *s64;
}

__global__ void hist_kernel(const void* __restrict__ edges, int E) {
    __shared__ int s64;
    int is64 = detect_is64_block(edges, &s64);
    int e = blockIdx.x * blockDim.x + threadIdx.x;
    if (e >= E) return;
    int dst;
    if (is64) dst = (int)((const long long*)edges)[E + e];
    else      dst = ((const int*)edges)[E + e];
    atomicAdd(&g_counts[dst], 1);
}

// ---------------- split helper -------------------------------------------
__device__ __forceinline__ void split2(float v, __half& h, __half& l) {
    h = __float2half_rn(v);
    l = __float2half_rn(v - __half2float(h));
}

// ---------------- fused: matprep(+split) + single-kernel scan -------------
__device__ __forceinline__ void grid_barrier_200() {
    __syncthreads();
    if (threadIdx.x == 0) {
        __threadfence();
        unsigned long long my = atomicAdd(&g_barctr, 1ULL) + 1ULL;
        unsigned long long target = ((my + SCB - 1) / SCB) * (unsigned long long)SCB;
        while (atomicAdd(&g_barctr, 0ULL) < target) { }
        __threadfence();
    }
    __syncthreads();
}

__global__ void scan_fused(const float* __restrict__ Wp,
                           const float* __restrict__ Wt,
                           const float* __restrict__ Wout,
                           const float* __restrict__ bout, int N) {
    int b = blockIdx.x, t = threadIdx.x;

    // ---- matprep on blocks 0..15 (4096 lanes): fold + fp16-split ----
    if (b < 16) {
        int id = b * 256 + t;
        int i = id >> 6, k = id & 63;
        float s1 = 0.f, s2 = 0.f;
#pragma unroll
        for (int m = 0; m < DD; m++) {
            s1 += Wp[1 * DD * DD + i * DD + m] * Wt[0 * DD * DD + m * DD + k];
            s2 += Wp[2 * DD * DD + i * DD + m] * Wt[1 * DD * DD + m * DD + k];
        }
        __half h, l;
        split2(s1, h, l);                     // layer-1 B = Wp1*Wt0
        g_Bh[id] = h; g_Bl[id] = l;
        split2(s2, h, l);                     // layer-2 B = Wp2*Wt1
        g_Bh[DD * DD + id] = h; g_Bl[DD * DD + id] = l;
        if (i == 0) {
            float sv = 0.f;
#pragma unroll
            for (int m = 0; m < DD; m++)
                sv += Wout[m] * Wt[2 * DD * DD + m * DD + k];
            g_v[k] = sv;
        }
        if (id == 0) g_bias = bout[0];
    }

    // ---- phase 1: block sum over its 512-element chunk ----
    __shared__ int sm[256];
    int base = b * 512 + t * 2;
    int c0 = (base < N) ? g_counts[base] : 0;
    int c1 = (base + 1 < N) ? g_counts[base + 1] : 0;
    int s = c0 + c1;
    sm[t] = s;
    __syncthreads();
    for (int off = 128; off; off >>= 1) {
        if (t < off) sm[t] += sm[t + off];
        __syncthreads();
    }
    if (t == 0) g_bsum[b] = sm[0];

    grid_barrier_200();

    // ---- phase 2a: block offset = exclusive prefix of g_bsum ----
    __shared__ int sb[256];
    sb[t] = (t < SCB) ? g_bsum[t] : 0;
    __syncthreads();
    for (int off = 1; off < 256; off <<= 1) {
        int v = (t >= off) ? sb[t - off] : 0;
        __syncthreads();
        sb[t] += v;
        __syncthreads();
    }
    int blockoff = (b == 0) ? 0 : sb[b - 1];
    if (b == SCB - 1 && t == 0) g_rowptr[N] = sb[SCB - 1];

    // ---- phase 2b: local exclusive scan + write + zero counts ----
    sm[t] = s;
    __syncthreads();
    for (int off = 1; off < 256; off <<= 1) {
        int v = (t >= off) ? sm[t - off] : 0;
        __syncthreads();
        sm[t] += v;
        __syncthreads();
    }
    int pre = sm[t] - s + blockoff;
    if (base < N)     { g_rowptr[base] = pre;          g_fill[base] = pre;          g_counts[base] = 0; }
    if (base + 1 < N) { g_rowptr[base + 1] = pre + c0; g_fill[base + 1] = pre + c0; g_counts[base + 1] = 0; }
}

__global__ void scatter_kernel(const void* __restrict__ edges, int E) {
    __shared__ int s64;
    int is64 = detect_is64_block(edges, &s64);
    int e = blockIdx.x * blockDim.x + threadIdx.x;
    if (e >= E) return;
    int src, dst;
    if (is64) {
        const long long* p = (const long long*)edges;
        src = (int)p[e]; dst = (int)p[E + e];
    } else {
        const int* p = (const int*)edges;
        src = p[e]; dst = p[E + e];
    }
    int pos = atomicAdd(&g_fill[dst], 1);
    g_esrc[pos] = src << 7;              // byte offset into fp16 rows (64*2B)
}

// ---------------- tensor-core split-fp16 GEMM core ------------------------
// D = Ah*Bh + Ah*Bl + Al*Bh (3x mma.m16n8k16, fp32 accum) ~ fp32 precision.
// Block: 128 thr = 4 warps; tile 64 rows x 64 cols; warp = 16 rows x 64 cols.
#define BST 72
#define MMA16816(c, a0, a1, a2, a3, b0, b1) \
    asm("mma.sync.aligned.m16n8k16.row.col.f32.f16.f16.f32 " \
        "{%0,%1,%2,%3}, {%4,%5,%6,%7}, {%8,%9}, {%0,%1,%2,%3};" \
        : "+f"(c[0]), "+f"(c[1]), "+f"(c[2]), "+f"(c[3]) \
        : "r"(a0), "r"(a1), "r"(a2), "r"(a3), "r"(b0), "r"(b1))

__device__ __forceinline__ void gemm_tc_main(
    __half (*sAh)[BST], __half (*sAl)[BST],
    __half (*sBh)[BST], __half (*sBl)[BST],
    __half* __restrict__ out, int base, int N, int t) {
    int w = t >> 5, lane = t & 31;
    int rA = 16 * w + (lane >> 2);
    int kq = (lane & 3) * 2;
    int nq = lane >> 2;

    float c[8][4];
#pragma unroll
    for (int nb = 0; nb < 8; nb++)
#pragma unroll
        for (int j = 0; j < 4; j++) c[nb][j] = 0.f;

#pragma unroll
    for (int kb = 0; kb < 4; kb++) {
        int k0 = kb * 16 + kq;
        unsigned ah0 = *(const unsigned*)&sAh[rA    ][k0];
        unsigned ah1 = *(const unsigned*)&sAh[rA + 8][k0];
        unsigned ah2 = *(const unsigned*)&sAh[rA    ][k0 + 8];
        unsigned ah3 = *(const unsigned*)&sAh[rA + 8][k0 + 8];
        unsigned al0 = *(const unsigned*)&sAl[rA    ][k0];
        unsigned al1 = *(const unsigned*)&sAl[rA + 8][k0];
        unsigned al2 = *(const unsigned*)&sAl[rA    ][k0 + 8];
        unsigned al3 = *(const unsigned*)&sAl[rA + 8][k0 + 8];
#pragma unroll
        for (int nb = 0; nb < 8; nb++) {
            int nr = nb * 8 + nq;
            unsigned bh0 = *(const unsigned*)&sBh[nr][k0];
            unsigned bh1 = *(const unsigned*)&sBh[nr][k0 + 8];
            unsigned bl0 = *(const unsigned*)&sBl[nr][k0];
            unsigned bl1 = *(const unsigned*)&sBl[nr][k0 + 8];
            MMA16816(c[nb], ah0, ah1, ah2, ah3, bh0, bh1);   // hi*hi
            MMA16816(c[nb], ah0, ah1, ah2, ah3, bl0, bl1);   // hi*lo
            MMA16816(c[nb], al0, al1, al2, al3, bh0, bh1);   // lo*hi
        }
    }

    int row0 = base + rA;
    int row1 = row0 + 8;
    int ncol = (lane & 3) * 2;
#pragma unroll
    for (int nb = 0; nb < 8; nb++) {
        if (row0 < N) {
            __half2 h = __floats2half2_rn(c[nb][0], c[nb][1]);
            *(unsigned*)&out[(size_t)row0 * DD + nb * 8 + ncol] = *(const unsigned*)&h;
        }
        if (row1 < N) {
            __half2 h = __floats2half2_rn(c[nb][2], c[nb][3]);
            *(unsigned*)&out[(size_t)row1 * DD + nb * 8 + ncol] = *(const unsigned*)&h;
        }
    }
}

// layers 1,2: A from pre-split halves, B from pre-split halves
__global__ void __launch_bounds__(128)
gemm_tc(const __half* __restrict__ Ah, const __half* __restrict__ Al,
        const __half* __restrict__ Bh, const __half* __restrict__ Bl,
        __half* __restrict__ out, int N) {
    __shared__ __half sAh[DD][BST], sAl[DD][BST];
    __shared__ __half sBh[DD][BST], sBl[DD][BST];
    int t = threadIdx.x;
    int base = blockIdx.x * DD;

#pragma unroll
    for (int i = 0; i < 16; i++) {
        int v = t + 128 * i;
        int arr = v >> 9;
        int v2 = v & 511;
        int row = v2 >> 3;
        int c = (v2 & 7) * 8;
        uint4 val = make_uint4(0u, 0u, 0u, 0u);
        __half* dst;
        if (arr == 0) {
            if (base + row < N) val = *(const uint4*)&Ah[(size_t)(base + row) * DD + c];
            dst = &sAh[row][c];
        } else if (arr == 1) {
            if (base + row < N) val = *(const uint4*)&Al[(size_t)(base + row) * DD + c];
            dst = &sAl[row][c];
        } else if (arr == 2) {
            val = *(const uint4*)&Bh[row * DD + c];
            dst = &sBh[row][c];
        } else {
            val = *(const uint4*)&Bl[row * DD + c];
            dst = &sBl[row][c];
        }
        *(uint4*)dst = val;
    }
    __syncthreads();
    gemm_tc_main(sAh, sAl, sBh, sBl, out, base, N, t);
}

// layer 0: A = fp32 x, B = fp32 Wp0; split in registers during staging.
__global__ void __launch_bounds__(128)
gemm_tc_f32(const float* __restrict__ A, const float* __restrict__ B,
            __half* __restrict__ out, int N) {
    __shared__ __half sAh[DD][BST], sAl[DD][BST];
    __shared__ __half sBh[DD][BST], sBl[DD][BST];
    int t = threadIdx.x;
    int base = blockIdx.x * DD;

    // 2048 float4 total (A 1024 + B 1024), 16 per thread
#pragma unroll
    for (int i = 0; i < 16; i++) {
        int v = t + 128 * i;
        int arr = v >> 10;              // 0 = A, 1 = B
        int v2 = v & 1023;
        int row = v2 >> 4;
        int c4 = (v2 & 15) * 4;
        float4 f = make_float4(0.f, 0.f, 0.f, 0.f);
        if (arr == 0) {
            if (base + row < N) f = *(const float4*)&A[(size_t)(base + row) * DD + c4];
        } else {
            f = *(const float4*)&B[row * DD + c4];
        }
        __half h[4], l[4];
        split2(f.x, h[0], l[0]); split2(f.y, h[1], l[1]);
        split2(f.z, h[2], l[2]); split2(f.w, h[3], l[3]);
        __half* dh = (arr == 0) ? &sAh[row][c4] : &sBh[row][c4];
        __half* dl = (arr == 0) ? &sAl[row][c4] : &sBl[row][c4];
        *(uint2*)dh = *(const uint2*)h;
        *(uint2*)dl = *(const uint2*)l;
    }
    __syncthreads();
    gemm_tc_main(sAh, sAl, sBh, sBl, out, base, N, t);
}

// ---------------- aggregation core (fp16 gather, L2-only loads) -----------
__device__ __forceinline__ void agg_core_h(const __half* __restrict__ yh,
                                           int beg, int end, int lane,
                                           __half2& m01, __half2& m23) {
    const __half2 ninf = __float2half2_rn(-INFINITY);
    m01 = ninf; m23 = ninf;
    const char* Y = (const char*)yh;
    int half_id = lane >> 4;
    int qb = (lane & 15) * 8;
    int p = beg;
    for (; p + 8 <= end; p += 8) {         // 4 edges per half-warp
        int o0 = __ldg(&g_esrc[p     + half_id]);
        int o1 = __ldg(&g_esrc[p + 2 + half_id]);
        int o2 = __ldg(&g_esrc[p + 4 + half_id]);
        int o3 = __ldg(&g_esrc[p + 6 + half_id]);
        uint2 a = __ldcg((const uint2*)(Y + o0 + qb));
        uint2 c = __ldcg((const uint2*)(Y + o1 + qb));
        uint2 d = __ldcg((const uint2*)(Y + o2 + qb));
        uint2 e = __ldcg((const uint2*)(Y + o3 + qb));
        m01 = __hmax2(m01, __hmax2(__hmax2(*(__half2*)&a.x, *(__half2*)&c.x),
                                   __hmax2(*(__half2*)&d.x, *(__half2*)&e.x)));
        m23 = __hmax2(m23, __hmax2(__hmax2(*(__half2*)&a.y, *(__half2*)&c.y),
                                   __hmax2(*(__half2*)&d.y, *(__half2*)&e.y)));
    }
    if (p + 4 <= end) {                    // 2 edges per half-warp
        int o0 = __ldg(&g_esrc[p     + half_id]);
        int o1 = __ldg(&g_esrc[p + 2 + half_id]);
        uint2 a = __ldcg((const uint2*)(Y + o0 + qb));
        uint2 c = __ldcg((const uint2*)(Y + o1 + qb));
        m01 = __hmax2(m01, __hmax2(*(__half2*)&a.x, *(__half2*)&c.x));
        m23 = __hmax2(m23, __hmax2(*(__half2*)&a.y, *(__half2*)&c.y));
        p += 4;
    }
    for (; p < end; p++) {                 // tail: both halves duplicate
        int o = __ldg(&g_esrc[p]);
        uint2 a = __ldcg((const uint2*)(Y + o + qb));
        m01 = __hmax2(m01, *(__half2*)&a.x);
        m23 = __hmax2(m23, *(__half2*)&a.y);
    }
    unsigned u01 = *(unsigned*)&m01, u23 = *(unsigned*)&m23;
    unsigned o01 = __shfl_xor_sync(0xffffffffu, u01, 16);
    unsigned o23 = __shfl_xor_sync(0xffffffffu, u23, 16);
    m01 = __hmax2(m01, *(__half2*)&o01);
    m23 = __hmax2(m23, *(__half2*)&o23);
}

// agg: out = split( max_{src} yh[src] - yh[i] )  into g_ah/g_al
__global__ void agg_kernel(const __half* __restrict__ yh, int N) {
    int wid = (blockIdx.x * blockDim.x + threadIdx.x) >> 5;
    int lane = threadIdx.x & 31;
    if (wid >= N) return;
    int beg = g_rowptr[wid];
    int end = g_rowptr[wid + 1];
    __half2 m01, m23;
    agg_core_h(yh, beg, end, lane, m01, m23);
    if (lane < 16) {
        int q = lane;
        float d0 = 0.f, d1 = 0.f, d2 = 0.f, d3 = 0.f;
        if (beg != end) {
            uint2 sp = *(const uint2*)&yh[(size_t)wid * DD + q * 4];
            float2 f01 = __half22float2(m01);
            float2 f23 = __half22float2(m23);
            float2 s01 = __half22float2(*(__half2*)&sp.x);
            float2 s23 = __half22float2(*(__half2*)&sp.y);
            d0 = f01.x - s01.x; d1 = f01.y - s01.y;
            d2 = f23.x - s23.x; d3 = f23.y - s23.y;
        }
        __half h[4], l[4];
        split2(d0, h[0], l[0]); split2(d1, h[1], l[1]);
        split2(d2, h[2], l[2]); split2(d3, h[3], l[3]);
        *(uint2*)&g_ah[(size_t)wid * DD + q * 4] = *(const uint2*)h;
        *(uint2*)&g_al[(size_t)wid * DD + q * 4] = *(const uint2*)l;
    }
}

// last layer: agg + dot with folded head vector + sigmoid, fused.
__global__ void agg_final_kernel(const __half* __restrict__ yh,
                                 float* __restrict__ out, int N) {
    int wid = (blockIdx.x * blockDim.x + threadIdx.x) >> 5;
    int lane = threadIdx.x & 31;
    if (wid >= N) return;
    int beg = g_rowptr[wid];
    int end = g_rowptr[wid + 1];
    __half2 m01, m23;
    agg_core_h(yh, beg, end, lane, m01, m23);
    int q = lane & 15;
    float p = 0.f;
    if (beg != end) {
        uint2 sp = *(const uint2*)&yh[(size_t)wid * DD + q * 4];
        float2 f01 = __half22float2(m01);
        float2 f23 = __half22float2(m23);
        float2 s01 = __half22float2(*(__half2*)&sp.x);
        float2 s23 = __half22float2(*(__half2*)&sp.y);
        float4 vv = *(const float4*)&g_v[q * 4];
        p = (f01.x - s01.x) * vv.x + (f01.y - s01.y) * vv.y
          + (f23.x - s23.x) * vv.z + (f23.y - s23.y) * vv.w;
    }
#pragma unroll
    for (int off = 8; off; off >>= 1)
        p += __shfl_xor_sync(0xffffffffu, p, off);
    if (lane == 0)
        out[wid] = 1.f / (1.f + expf(-(p + g_bias)));
}

extern "C" void kernel_launch(void* const* d_in, const int* in_sizes, int n_in,
                              void* d_out, int out_size) {
    const float* x     = (const float*)d_in[0];
    const void*  edges = d_in[1];
    const float* Wp    = (const float*)d_in[2];
    const float* Wt    = (const float*)d_in[3];
    const float* Wout  = (const float*)d_in[4];
    const float* bout  = (const float*)d_in[5];
    float* out = (float*)d_out;

    int N = in_sizes[0] / DD;
    int E = in_sizes[1] / 2;

    __half *yhp, *ahp, *alp, *bhp, *blp;
    cudaGetSymbolAddress((void**)&yhp, g_yh);
    cudaGetSymbolAddress((void**)&ahp, g_ah);
    cudaGetSymbolAddress((void**)&alp, g_al);
    cudaGetSymbolAddress((void**)&bhp, g_Bh);
    cudaGetSymbolAddress((void**)&blp, g_Bl);

    const int TB = 256;
    int ebl = (E + TB - 1) / TB;
    int wbl = ((N * 32) + TB - 1) / TB;   // warp-per-node grids
    int gbl = (N + DD - 1) / DD;          // 64-row GEMM tiles

    hist_kernel<<<ebl, TB>>>(edges, E);
    scan_fused<<<SCB, 256>>>(Wp, Wt, Wout, bout, N);
    scatter_kernel<<<ebl, TB>>>(edges, E);

    // layer 0: yh = x @ Wp0^T  (fp32 inputs split in-kernel)
    gemm_tc_f32<<<gbl, 128>>>(x, Wp, yhp, N);
    agg_kernel<<<wbl, TB>>>(yhp, N);
    // layer 1: yh = agg @ (Wp1 Wt0)^T
    gemm_tc<<<gbl, 128>>>(ahp, alp, bhp, blp, yhp, N);
    agg_kernel<<<wbl, TB>>>(yhp, N);
    // layer 2 + head
    gemm_tc<<<gbl, 128>>>(ahp, alp, bhp + DD * DD, blp + DD * DD, yhp, N);
    agg_final_kernel<<<wbl, TB>>>(yhp, out, N);
}